// round 9
// baseline (speedup 1.0000x reference)
#include <cuda_runtime.h>
#include <math.h>

#define B_  4
#define S_  2048
#define HID 1024
#define NH  16
#define HD  64

typedef unsigned long long u64;
typedef unsigned int u32;

// Scratch (device globals: no allocation allowed in kernel_launch).
__device__ __align__(128) float g_Q[B_ * NH * S_ * HD];
__device__ __align__(128) float g_K[B_ * NH * S_ * HD];
__device__ __align__(128) float g_V[B_ * NH * S_ * HD];
// tf32 hi/lo split operands, packed (hi in low 32b, lo in high 32b).
__device__ __align__(128) u64 g_x2[(size_t)B_ * S_ * HID];      // [m][k] 64MB
__device__ __align__(128) u64 g_w2[(size_t)3 * HID * HID];      // [z][k][n] 24MB

// ---- packed f32x2 helpers (attention kernel) ------------------------------
__device__ __forceinline__ void ffma2(u64& acc, u64 a, u64 b) {
    asm("fma.rn.f32x2 %0, %1, %2, %0;" : "+l"(acc) : "l"(a), "l"(b));
}
__device__ __forceinline__ u64 mul2(u64 a, u64 b) {
    u64 r; asm("mul.rn.f32x2 %0, %1, %2;" : "=l"(r) : "l"(a), "l"(b)); return r;
}
__device__ __forceinline__ u64 dup2(float f) {
    u64 r; unsigned u = __float_as_uint(f);
    asm("mov.b64 %0, {%1, %1};" : "=l"(r) : "r"(u)); return r;
}
__device__ __forceinline__ u64 pk2(float a, float b) {
    u64 r;
    asm("mov.b64 %0, {%1, %2};" : "=l"(r)
        : "r"(__float_as_uint(a)), "r"(__float_as_uint(b)));
    return r;
}
__device__ __forceinline__ float2 unpk(u64 a) {
    unsigned lo, hi;
    asm("mov.b64 {%0, %1}, %2;" : "=r"(lo), "=r"(hi) : "l"(a));
    return make_float2(__uint_as_float(lo), __uint_as_float(hi));
}
__device__ __forceinline__ void unpk2u(u64 a, u32& lo, u32& hi) {
    asm("mov.b64 {%0, %1}, %2;" : "=r"(lo), "=r"(hi) : "l"(a));
}
__device__ __forceinline__ int kidx(int tx, int j) {
    return 2 * tx + (j & 1) + 32 * (j >> 1);
}

// ---- tf32 helpers ---------------------------------------------------------
__device__ __forceinline__ u32 tf32r(float f) {
    u32 r; asm("cvt.rna.tf32.f32 %0, %1;" : "=r"(r) : "f"(f)); return r;
}
__device__ __forceinline__ u64 split_tf32(float v) {
    u32 hb = tf32r(v);
    float hf = __uint_as_float(hb);
    u32 lb = tf32r(v - hf);
    u64 r;
    asm("mov.b64 %0, {%1, %2};" : "=l"(r) : "r"(hb), "r"(lb));
    return r;
}
__device__ __forceinline__ void mma_tf32(float* c, u32 a0, u32 a1, u32 a2,
                                         u32 a3, u32 b0, u32 b1) {
    asm("mma.sync.aligned.m16n8k8.row.col.f32.tf32.tf32.f32 "
        "{%0,%1,%2,%3}, {%4,%5,%6,%7}, {%8,%9}, {%0,%1,%2,%3};"
        : "+f"(c[0]), "+f"(c[1]), "+f"(c[2]), "+f"(c[3])
        : "r"(a0), "r"(a1), "r"(a2), "r"(a3), "r"(b0), "r"(b1));
}

// ---------------------------------------------------------------------------
// Prep: split x and W into packed tf32 (hi, lo) u64 arrays.
// ---------------------------------------------------------------------------
__global__ __launch_bounds__(256) void split_x(const float* __restrict__ x) {
    size_t i = (size_t)blockIdx.x * 256 + threadIdx.x;   // float4 index
    float4 v = ((const float4*)x)[i];
    u64* d = g_x2 + i * 4;
    d[0] = split_tf32(v.x);
    d[1] = split_tf32(v.y);
    d[2] = split_tf32(v.z);
    d[3] = split_tf32(v.w);
}

__global__ __launch_bounds__(256) void split_w(
    const float* __restrict__ Wq, const float* __restrict__ Wk,
    const float* __restrict__ Wv)
{
    const float* W = (blockIdx.y == 0) ? Wq : (blockIdx.y == 1) ? Wk : Wv;
    size_t i = (size_t)blockIdx.x * 256 + threadIdx.x;   // float4 index
    float4 v = ((const float4*)W)[i];
    u64* d = g_w2 + (size_t)blockIdx.y * HID * HID + i * 4;
    d[0] = split_tf32(v.x);
    d[1] = split_tf32(v.y);
    d[2] = split_tf32(v.z);
    d[3] = split_tf32(v.w);
}

// ---------------------------------------------------------------------------
// Kernel 1: tf32 HMMA projection GEMM, 3-pass hi/lo split.
// Block 128m x 128n, 256 threads, warp = 64m x 32n of m16n8k8 tiles.
// ---------------------------------------------------------------------------
#define XROW 68    // xs2 row stride in u64 (64 + 4): A-frag LDS.64 at floor
#define WROW 136   // ws2 row stride in u64 (128 + 8): B-frag LDS.64 at floor

__global__ __launch_bounds__(256) void qkv_gemm_tf32(
    const float* __restrict__ bq, const float* __restrict__ bk,
    const float* __restrict__ bv)
{
    extern __shared__ u64 smu[];
    u64* xs2 = smu;                 // [128][XROW]
    u64* ws2 = smu + 128 * XROW;    // [64][WROW]

    const int z = blockIdx.z;
    const u64* Wz = g_w2 + (size_t)z * HID * HID;
    const float* bias = (z == 0) ? bq : (z == 1) ? bk : bv;
    float* dst        = (z == 0) ? g_Q : (z == 1) ? g_K : g_V;

    const int n0 = blockIdx.x * 128;
    const int m0 = blockIdx.y * 128;
    const int tid = threadIdx.x;
    const int lane = tid & 31;
    const int wid = tid >> 5;
    const int wm = wid & 1;         // 2 m-halves of 64
    const int wn = wid >> 1;        // 4 n-quarters of 32
    const int gr = lane >> 2;       // groupID (0..7)
    const int gc = lane & 3;        // thread-in-group (0..3)

    float acc[4][4][4] = {};        // [tm][tn][c0..c3]

    for (int ch = 0; ch < 16; ch++) {
        const int k0 = ch * 64;
        __syncthreads();
        // xs2: 128 rows x 64 u64  (8192 entries, 32 iters x 256 threads)
        #pragma unroll
        for (int i = 0; i < 32; i++) {
            int lin = tid + i * 256;
            int row = lin >> 6, c = lin & 63;
            xs2[row * XROW + c] = g_x2[(size_t)(m0 + row) * HID + k0 + c];
        }
        // ws2: 64 rows x 128 u64  (8192 entries)
        #pragma unroll
        for (int i = 0; i < 32; i++) {
            int lin = tid + i * 256;
            int row = lin >> 7, c = lin & 127;
            ws2[row * WROW + c] = Wz[(size_t)(k0 + row) * HID + n0 + c];
        }
        __syncthreads();

        #pragma unroll
        for (int ks = 0; ks < 8; ks++) {
            const int kk = ks * 8;
            // A fragments (4 m-tiles), hi/lo unpacked
            u32 ah[4][4], al[4][4];
            #pragma unroll
            for (int tm = 0; tm < 4; tm++) {
                int r = wm * 64 + tm * 16 + gr;
                u64 v0 = xs2[(r)     * XROW + kk + gc];
                u64 v1 = xs2[(r + 8) * XROW + kk + gc];
                u64 v2 = xs2[(r)     * XROW + kk + gc + 4];
                u64 v3 = xs2[(r + 8) * XROW + kk + gc + 4];
                unpk2u(v0, ah[tm][0], al[tm][0]);
                unpk2u(v1, ah[tm][1], al[tm][1]);
                unpk2u(v2, ah[tm][2], al[tm][2]);
                unpk2u(v3, ah[tm][3], al[tm][3]);
            }
            // B fragments (4 n-tiles)
            u32 bh[4][2], bl[4][2];
            #pragma unroll
            for (int tn = 0; tn < 4; tn++) {
                int ccol = wn * 32 + tn * 8 + gr;
                u64 v0 = ws2[(kk + gc)     * WROW + ccol];
                u64 v1 = ws2[(kk + gc + 4) * WROW + ccol];
                unpk2u(v0, bh[tn][0], bl[tn][0]);
                unpk2u(v1, bh[tn][1], bl[tn][1]);
            }
            // 3-pass MMA
            #pragma unroll
            for (int tm = 0; tm < 4; tm++)
                #pragma unroll
                for (int tn = 0; tn < 4; tn++) {
                    float* c = acc[tm][tn];
                    mma_tf32(c, ah[tm][0], ah[tm][1], ah[tm][2], ah[tm][3],
                             bh[tn][0], bh[tn][1]);
                    mma_tf32(c, ah[tm][0], ah[tm][1], ah[tm][2], ah[tm][3],
                             bl[tn][0], bl[tn][1]);
                    mma_tf32(c, al[tm][0], al[tm][1], al[tm][2], al[tm][3],
                             bh[tn][0], bh[tn][1]);
                }
        }
    }

    // Epilogue: scatter into [B,H,S,D] with bias.
    #pragma unroll
    for (int tm = 0; tm < 4; tm++) {
        #pragma unroll
        for (int half = 0; half < 2; half++) {
            int m = m0 + wm * 64 + tm * 16 + gr + half * 8;
            int b = m >> 11;
            int s = m & (S_ - 1);
            #pragma unroll
            for (int tn = 0; tn < 4; tn++) {
                int n = n0 + wn * 32 + tn * 8 + 2 * gc;
                float2 bb = *(const float2*)&bias[n];
                float2 r;
                r.x = acc[tm][tn][half * 2 + 0] + bb.x;
                r.y = acc[tm][tn][half * 2 + 1] + bb.y;
                int h = n >> 6, d = n & 63;
                *(float2*)&dst[(((size_t)b * NH + h) * S_ + s) * HD + d] = r;
            }
        }
    }
}

// ---------------------------------------------------------------------------
// Kernel 2: flash attention (exact Round-4 kernel — proven 2611us config).
// ---------------------------------------------------------------------------
#define QP 130
#define KP 65
#define PP 130

__global__ __launch_bounds__(256, 1) void attn_kernel(
    const float* __restrict__ T,
    const int*   __restrict__ mask,
    const float* __restrict__ alpha_p,
    float*       __restrict__ out)
{
    extern __shared__ float sma[];
    float* Qt = sma;
    float* Ks = Qt + 64 * QP;
    float* Vs = Ks + 128 * KP;
    float* Pt = Vs + 128 * 64;

    const int h  = blockIdx.x;
    const int q0 = blockIdx.y * 128;
    const int b  = blockIdx.z;
    const int tid = threadIdx.x;
    const int tx = tid & 15;
    const int ty = tid >> 4;

    const float nalpha = -fabsf(*alpha_p);
    const float* Qg = g_Q + ((size_t)b * NH + h) * S_ * HD;
    const float* Kg = g_K + ((size_t)b * NH + h) * S_ * HD;
    const float* Vg = g_V + ((size_t)b * NH + h) * S_ * HD;
    const float* Tb = T    + (size_t)b * S_ * S_;
    const int*   Mb = mask + (size_t)b * S_ * S_;

    #pragma unroll
    for (int i = 0; i < 8; i++) {
        int lin = tid + i * 256;
        int q = lin >> 4, c = lin & 15;
        float4 v = *(const float4*)&Qg[(size_t)(q0 + q) * HD + c * 4];
        Qt[(c * 4 + 0) * QP + q] = v.x;
        Qt[(c * 4 + 1) * QP + q] = v.y;
        Qt[(c * 4 + 2) * QP + q] = v.z;
        Qt[(c * 4 + 3) * QP + q] = v.w;
    }

    float m_run[8], l_run[8];
    u64 o2[4][4] = {};
    #pragma unroll
    for (int r = 0; r < 8; r++) { m_run[r] = -INFINITY; l_run[r] = 0.f; }

    for (int k0 = 0; k0 < S_; k0 += 128) {
        __syncthreads();
        #pragma unroll
        for (int i = 0; i < 8; i++) {
            int lin = tid + i * 256;
            int k = lin >> 4, c = lin & 15;
            float4 kv = *(const float4*)&Kg[(size_t)(k0 + k) * HD + c * 4];
            Ks[k * KP + c * 4 + 0] = kv.x;
            Ks[k * KP + c * 4 + 1] = kv.y;
            Ks[k * KP + c * 4 + 2] = kv.z;
            Ks[k * KP + c * 4 + 3] = kv.w;
            float4 vv = *(const float4*)&Vg[(size_t)(k0 + k) * HD + c * 4];
            *(float4*)&Vs[k * 64 + c * 4] = vv;
        }
        __syncthreads();

        u64 acc2[4][8] = {};
        #pragma unroll 8
        for (int c = 0; c < 64; c++) {
            u64 qp[4];
            #pragma unroll
            for (int m = 0; m < 4; m++)
                qp[m] = *(const u64*)&Qt[c * QP + ty * 8 + 2 * m];
            u64 kd[8];
            #pragma unroll
            for (int j = 0; j < 8; j++)
                kd[j] = dup2(Ks[kidx(tx, j) * KP + c]);
            #pragma unroll
            for (int m = 0; m < 4; m++)
                #pragma unroll
                for (int j = 0; j < 8; j++)
                    ffma2(acc2[m][j], qp[m], kd[j]);
        }

        #pragma unroll
        for (int m = 0; m < 4; m++) {
            float2 sc[8];
            #pragma unroll
            for (int j = 0; j < 8; j++) sc[j] = unpk(acc2[m][j]);
            float corr2[2];
            #pragma unroll
            for (int e = 0; e < 2; e++) {
                int r = 2 * m + e;
                int qg = q0 + ty * 8 + r;
                float v[8];
                #pragma unroll
                for (int jj = 0; jj < 4; jj++) {
                    size_t off = (size_t)qg * S_ + k0 + 2 * tx + 32 * jj;
                    float2 t2 = *(const float2*)&Tb[off];
                    int2  mm2 = *(const int2*)  &Mb[off];
                    float s0 = e ? sc[2 * jj].y     : sc[2 * jj].x;
                    float s1 = e ? sc[2 * jj + 1].y : sc[2 * jj + 1].x;
                    v[2 * jj]     = (mm2.x == 0) ? -1e9f : s0 * 0.125f + nalpha * t2.x;
                    v[2 * jj + 1] = (mm2.y == 0) ? -1e9f : s1 * 0.125f + nalpha * t2.y;
                }
                float mloc = v[0];
                #pragma unroll
                for (int j = 1; j < 8; j++) mloc = fmaxf(mloc, v[j]);
                mloc = fmaxf(mloc, __shfl_xor_sync(0xFFFFFFFFu, mloc, 1));
                mloc = fmaxf(mloc, __shfl_xor_sync(0xFFFFFFFFu, mloc, 2));
                mloc = fmaxf(mloc, __shfl_xor_sync(0xFFFFFFFFu, mloc, 4));
                mloc = fmaxf(mloc, __shfl_xor_sync(0xFFFFFFFFu, mloc, 8));
                float mnew = fmaxf(m_run[r], mloc);
                float corr = __expf(m_run[r] - mnew);
                float ps = 0.f;
                #pragma unroll
                for (int j = 0; j < 8; j++) {
                    v[j] = __expf(v[j] - mnew);
                    ps += v[j];
                }
                ps += __shfl_xor_sync(0xFFFFFFFFu, ps, 1);
                ps += __shfl_xor_sync(0xFFFFFFFFu, ps, 2);
                ps += __shfl_xor_sync(0xFFFFFFFFu, ps, 4);
                ps += __shfl_xor_sync(0xFFFFFFFFu, ps, 8);
                l_run[r] = l_run[r] * corr + ps;
                m_run[r] = mnew;
                corr2[e] = corr;
                #pragma unroll
                for (int j = 0; j < 8; j++)
                    Pt[kidx(tx, j) * PP + ty * 8 + r] = v[j];
            }
            u64 c2 = pk2(corr2[0], corr2[1]);
            #pragma unroll
            for (int j = 0; j < 4; j++) o2[m][j] = mul2(o2[m][j], c2);
        }
        __syncthreads();

        #pragma unroll 4
        for (int k = 0; k < 128; k++) {
            u64 p2[4];
            #pragma unroll
            for (int m = 0; m < 4; m++)
                p2[m] = *(const u64*)&Pt[k * PP + ty * 8 + 2 * m];
            u64 vd[4];
            #pragma unroll
            for (int j = 0; j < 4; j++)
                vd[j] = dup2(Vs[k * 64 + tx + 16 * j]);
            #pragma unroll
            for (int m = 0; m < 4; m++)
                #pragma unroll
                for (int j = 0; j < 4; j++)
                    ffma2(o2[m][j], p2[m], vd[j]);
        }
    }

    #pragma unroll
    for (int m = 0; m < 4; m++) {
        float inv0 = 1.f / l_run[2 * m];
        float inv1 = 1.f / l_run[2 * m + 1];
        int s0 = q0 + ty * 8 + 2 * m;
        #pragma unroll
        for (int j = 0; j < 4; j++) {
            float2 ov = unpk(o2[m][j]);
            int d = h * HD + tx + 16 * j;
            out[((size_t)b * S_ + s0)     * HID + d] = ov.x * inv0;
            out[((size_t)b * S_ + s0 + 1) * HID + d] = ov.y * inv1;
        }
    }
}

// ---------------------------------------------------------------------------
// Launch
// ---------------------------------------------------------------------------
extern "C" void kernel_launch(void* const* d_in, const int* in_sizes, int n_in,
                              void* d_out, int out_size)
{
    const float* x     = (const float*)d_in[0];
    const float* T     = (const float*)d_in[1];
    const int*   mask  = (const int*)  d_in[2];
    const float* Wq    = (const float*)d_in[3];
    const float* bq    = (const float*)d_in[4];
    const float* Wk    = (const float*)d_in[5];
    const float* bk    = (const float*)d_in[6];
    const float* Wv    = (const float*)d_in[7];
    const float* bv    = (const float*)d_in[8];
    const float* alpha = (const float*)d_in[9];
    float* out = (float*)d_out;

    split_x<<<(B_ * S_ * HID / 4) / 256, 256>>>(x);
    dim3 gw((HID * HID / 4) / 256, 3);
    split_w<<<gw, 256>>>(Wq, Wk, Wv);

    const int smem_g = (128 * XROW + 64 * WROW) * (int)sizeof(u64);  // 139264
    cudaFuncSetAttribute(qkv_gemm_tf32,
                         cudaFuncAttributeMaxDynamicSharedMemorySize, smem_g);
    dim3 g1(HID / 128, (B_ * S_) / 128, 3);
    qkv_gemm_tf32<<<g1, 256, smem_g>>>(bq, bk, bv);

    const int smem_a = (64 * QP + 128 * KP + 128 * 64 + 128 * PP)
                       * (int)sizeof(float);                         // 165888
    cudaFuncSetAttribute(attn_kernel,
                         cudaFuncAttributeMaxDynamicSharedMemorySize, smem_a);
    dim3 g2(NH, S_ / 128, B_);
    attn_kernel<<<g2, 256, smem_a>>>(T, mask, alpha, out);
}

// round 10
// speedup vs baseline: 1.0507x; 1.0507x over previous
#include <cuda_runtime.h>
#include <math.h>

#define B_  4
#define S_  2048
#define HID 1024
#define NH  16
#define HD  64

typedef unsigned long long u64;

// Scratch (device globals: no allocation allowed in kernel_launch).
__device__ __align__(128) float g_Q[B_ * NH * S_ * HD];
__device__ __align__(128) float g_K[B_ * NH * S_ * HD];
__device__ __align__(128) float g_V[B_ * NH * S_ * HD];

// ---- packed f32x2 helpers -------------------------------------------------
__device__ __forceinline__ void ffma2(u64& acc, u64 a, u64 b) {
    asm("fma.rn.f32x2 %0, %1, %2, %0;" : "+l"(acc) : "l"(a), "l"(b));
}
__device__ __forceinline__ u64 mul2(u64 a, u64 b) {
    u64 r; asm("mul.rn.f32x2 %0, %1, %2;" : "=l"(r) : "l"(a), "l"(b)); return r;
}
__device__ __forceinline__ u64 dup2(float f) {
    u64 r; unsigned u = __float_as_uint(f);
    asm("mov.b64 %0, {%1, %1};" : "=l"(r) : "r"(u)); return r;
}
__device__ __forceinline__ u64 pk2(float a, float b) {
    u64 r;
    asm("mov.b64 %0, {%1, %2};" : "=l"(r)
        : "r"(__float_as_uint(a)), "r"(__float_as_uint(b)));
    return r;
}
__device__ __forceinline__ float2 unpk(u64 a) {
    unsigned lo, hi;
    asm("mov.b64 {%0, %1}, %2;" : "=r"(lo), "=r"(hi) : "l"(a));
    return make_float2(__uint_as_float(lo), __uint_as_float(hi));
}
// Thread's k-column set in the attention score tile (bank-conflict-free).
__device__ __forceinline__ int kidx(int tx, int j) {
    return 2 * tx + (j & 1) + 32 * (j >> 1);
}

// ---------------------------------------------------------------------------
// Kernel 1: y = x @ W + b  ->  [B,H,S,D].  128x128 tile, 256 threads,
// microtile 8m x 8n; FFMA2 packed along n. (Proven R4 kernel.)
// ---------------------------------------------------------------------------
#define XP 65     // xs row pad ([m][k])
#define WP 132    // ws row pad ([k][n]), 16B-aligned rows

__global__ __launch_bounds__(256, 2) void qkv_gemm(
    const float* __restrict__ x,
    const float* __restrict__ Wq, const float* __restrict__ bq,
    const float* __restrict__ Wk, const float* __restrict__ bk,
    const float* __restrict__ Wv, const float* __restrict__ bv)
{
    extern __shared__ float smg[];
    float* xs = smg;              // 128 x XP
    float* ws = smg + 128 * XP;   // 64 x WP

    const int z = blockIdx.z;
    const float* W    = (z == 0) ? Wq : (z == 1) ? Wk : Wv;
    const float* bias = (z == 0) ? bq : (z == 1) ? bk : bv;
    float* dst        = (z == 0) ? g_Q : (z == 1) ? g_K : g_V;

    const int n0 = blockIdx.x * 128;
    const int m0 = blockIdx.y * 128;
    const int tid = threadIdx.x;
    const int tx = tid & 15;
    const int ty = tid >> 4;

    u64 acc2[8][4] = {};

    for (int k0 = 0; k0 < HID; k0 += 64) {
        __syncthreads();
        #pragma unroll
        for (int i = 0; i < 8; i++) {
            int lin = tid + i * 256;
            int r = lin >> 4, c = lin & 15;          // x: 128 rows x 16 chunks
            float4 xv = *(const float4*)&x[(size_t)(m0 + r) * HID + k0 + c * 4];
            xs[r * XP + c * 4 + 0] = xv.x;
            xs[r * XP + c * 4 + 1] = xv.y;
            xs[r * XP + c * 4 + 2] = xv.z;
            xs[r * XP + c * 4 + 3] = xv.w;
            int rw = lin >> 5, cw = lin & 31;        // W: 64 rows x 32 chunks
            float4 wv = *(const float4*)&W[(size_t)(k0 + rw) * HID + n0 + cw * 4];
            *(float4*)&ws[rw * WP + cw * 4] = wv;
        }
        __syncthreads();

        #pragma unroll 8
        for (int c = 0; c < 64; c++) {
            u64 wp[4];
            #pragma unroll
            for (int j = 0; j < 4; j++)
                wp[j] = *(const u64*)&ws[c * WP + 2 * tx + 32 * j];
            u64 xd[8];
            #pragma unroll
            for (int i = 0; i < 8; i++)
                xd[i] = dup2(xs[(ty * 8 + i) * XP + c]);
            #pragma unroll
            for (int i = 0; i < 8; i++)
                #pragma unroll
                for (int j = 0; j < 4; j++)
                    ffma2(acc2[i][j], xd[i], wp[j]);
        }
    }

    #pragma unroll
    for (int i = 0; i < 8; i++) {
        int m = m0 + ty * 8 + i;
        int b = m >> 11;
        int s = m & (S_ - 1);
        #pragma unroll
        for (int j = 0; j < 4; j++) {
            int n = n0 + 2 * tx + 32 * j;
            float2 bb = *(const float2*)&bias[n];
            float2 r = unpk(acc2[i][j]);
            r.x += bb.x; r.y += bb.y;
            int h = n >> 6, d = n & 63;
            *(float2*)&dst[(((size_t)b * NH + h) * S_ + s) * HD + d] = r;
        }
    }
}

// ---------------------------------------------------------------------------
// Kernel 2: flash attention, 128q x 128k tiles, 512 threads (16 warps/SM).
// Per-thread microtile: 4 q-rows (2 packed pairs) x 8 k-cols.
// ---------------------------------------------------------------------------
#define QP 130    // Qt row pad ([d][q])
#define KP 65     // Ks row pad ([k][d])
#define PP 130    // Pt row pad ([k][q])

__global__ __launch_bounds__(512, 1) void attn_kernel(
    const float* __restrict__ T,
    const int*   __restrict__ mask,
    const float* __restrict__ alpha_p,
    float*       __restrict__ out)
{
    extern __shared__ float sma[];
    float* Qt = sma;                       // 64 x QP
    float* Ks = Qt + 64 * QP;              // 128 x KP
    float* Vs = Ks + 128 * KP;             // 128 x 64
    float* Pt = Vs + 128 * 64;             // 128 x PP

    const int h  = blockIdx.x;             // head fastest: T/mask L2 reuse
    const int q0 = blockIdx.y * 128;
    const int b  = blockIdx.z;
    const int tid = threadIdx.x;
    const int tx = tid & 15;
    const int ty = tid >> 4;               // 0..31, 4 q-rows each

    const float nalpha = -fabsf(*alpha_p);
    const float* Qg = g_Q + ((size_t)b * NH + h) * S_ * HD;
    const float* Kg = g_K + ((size_t)b * NH + h) * S_ * HD;
    const float* Vg = g_V + ((size_t)b * NH + h) * S_ * HD;
    const float* Tb = T    + (size_t)b * S_ * S_;
    const int*   Mb = mask + (size_t)b * S_ * S_;

    // Q -> Qt[d][q] (transposed once per block)
    #pragma unroll
    for (int i = 0; i < 4; i++) {
        int lin = tid + i * 512;
        int q = lin >> 4, c = lin & 15;
        float4 v = *(const float4*)&Qg[(size_t)(q0 + q) * HD + c * 4];
        Qt[(c * 4 + 0) * QP + q] = v.x;
        Qt[(c * 4 + 1) * QP + q] = v.y;
        Qt[(c * 4 + 2) * QP + q] = v.z;
        Qt[(c * 4 + 3) * QP + q] = v.w;
    }

    float m_run[4], l_run[4];
    u64 o2[2][4] = {};
    #pragma unroll
    for (int r = 0; r < 4; r++) { m_run[r] = -INFINITY; l_run[r] = 0.f; }

    for (int k0 = 0; k0 < S_; k0 += 128) {
        __syncthreads();   // prior-iter Ks/Vs/Pt reads done (covers Qt on iter 0)
        #pragma unroll
        for (int i = 0; i < 4; i++) {
            int lin = tid + i * 512;
            int k = lin >> 4, c = lin & 15;
            float4 kv = *(const float4*)&Kg[(size_t)(k0 + k) * HD + c * 4];
            Ks[k * KP + c * 4 + 0] = kv.x;
            Ks[k * KP + c * 4 + 1] = kv.y;
            Ks[k * KP + c * 4 + 2] = kv.z;
            Ks[k * KP + c * 4 + 3] = kv.w;
            float4 vv = *(const float4*)&Vg[(size_t)(k0 + k) * HD + c * 4];
            *(float4*)&Vs[k * 64 + c * 4] = vv;
        }
        __syncthreads();

        // ---- scores: 2 q-pairs (packed) x 8 k-columns, over d ----
        u64 acc2[2][8] = {};
        #pragma unroll 8
        for (int c = 0; c < 64; c++) {
            u64 qp[2];
            #pragma unroll
            for (int m = 0; m < 2; m++)
                qp[m] = *(const u64*)&Qt[c * QP + ty * 4 + 2 * m];
            u64 kd[8];
            #pragma unroll
            for (int j = 0; j < 8; j++)
                kd[j] = dup2(Ks[kidx(tx, j) * KP + c]);
            #pragma unroll
            for (int m = 0; m < 2; m++)
                #pragma unroll
                for (int j = 0; j < 8; j++)
                    ffma2(acc2[m][j], qp[m], kd[j]);
        }

        // ---- bias + mask + online softmax ----
        #pragma unroll
        for (int m = 0; m < 2; m++) {
            float2 sc[8];
            #pragma unroll
            for (int j = 0; j < 8; j++) sc[j] = unpk(acc2[m][j]);
            float corr2[2];
            #pragma unroll
            for (int e = 0; e < 2; e++) {
                int r = 2 * m + e;
                int qg = q0 + ty * 4 + r;
                float v[8];
                #pragma unroll
                for (int jj = 0; jj < 4; jj++) {
                    size_t off = (size_t)qg * S_ + k0 + 2 * tx + 32 * jj;
                    float2 t2 = *(const float2*)&Tb[off];
                    int2  mm2 = *(const int2*)  &Mb[off];
                    float s0 = e ? sc[2 * jj].y     : sc[2 * jj].x;
                    float s1 = e ? sc[2 * jj + 1].y : sc[2 * jj + 1].x;
                    v[2 * jj]     = (mm2.x == 0) ? -1e9f : s0 * 0.125f + nalpha * t2.x;
                    v[2 * jj + 1] = (mm2.y == 0) ? -1e9f : s1 * 0.125f + nalpha * t2.y;
                }
                float mloc = v[0];
                #pragma unroll
                for (int j = 1; j < 8; j++) mloc = fmaxf(mloc, v[j]);
                mloc = fmaxf(mloc, __shfl_xor_sync(0xFFFFFFFFu, mloc, 1));
                mloc = fmaxf(mloc, __shfl_xor_sync(0xFFFFFFFFu, mloc, 2));
                mloc = fmaxf(mloc, __shfl_xor_sync(0xFFFFFFFFu, mloc, 4));
                mloc = fmaxf(mloc, __shfl_xor_sync(0xFFFFFFFFu, mloc, 8));
                float mnew = fmaxf(m_run[r], mloc);
                float corr = __expf(m_run[r] - mnew);   // 0 on first tile
                float ps = 0.f;
                #pragma unroll
                for (int j = 0; j < 8; j++) {
                    v[j] = __expf(v[j] - mnew);
                    ps += v[j];
                }
                ps += __shfl_xor_sync(0xFFFFFFFFu, ps, 1);
                ps += __shfl_xor_sync(0xFFFFFFFFu, ps, 2);
                ps += __shfl_xor_sync(0xFFFFFFFFu, ps, 4);
                ps += __shfl_xor_sync(0xFFFFFFFFu, ps, 8);
                l_run[r] = l_run[r] * corr + ps;
                m_run[r] = mnew;
                corr2[e] = corr;
                #pragma unroll
                for (int j = 0; j < 8; j++)
                    Pt[kidx(tx, j) * PP + ty * 4 + r] = v[j];
            }
            u64 c2 = pk2(corr2[0], corr2[1]);
            #pragma unroll
            for (int j = 0; j < 4; j++) o2[m][j] = mul2(o2[m][j], c2);
        }
        __syncthreads();

        // ---- O += P @ V : 2 q-pairs (packed) x 4 d-columns, over k ----
        #pragma unroll 4
        for (int k = 0; k < 128; k++) {
            u64 p2[2];
            #pragma unroll
            for (int m = 0; m < 2; m++)
                p2[m] = *(const u64*)&Pt[k * PP + ty * 4 + 2 * m];
            u64 vd[4];
            #pragma unroll
            for (int j = 0; j < 4; j++)
                vd[j] = dup2(Vs[k * 64 + tx + 16 * j]);
            #pragma unroll
            for (int m = 0; m < 2; m++)
                #pragma unroll
                for (int j = 0; j < 4; j++)
                    ffma2(o2[m][j], p2[m], vd[j]);
        }
    }

    // ---- epilogue ----
    #pragma unroll
    for (int m = 0; m < 2; m++) {
        float inv0 = 1.f / l_run[2 * m];
        float inv1 = 1.f / l_run[2 * m + 1];
        int s0 = q0 + ty * 4 + 2 * m;
        #pragma unroll
        for (int j = 0; j < 4; j++) {
            float2 ov = unpk(o2[m][j]);
            int d = h * HD + tx + 16 * j;
            out[((size_t)b * S_ + s0)     * HID + d] = ov.x * inv0;
            out[((size_t)b * S_ + s0 + 1) * HID + d] = ov.y * inv1;
        }
    }
}

// ---------------------------------------------------------------------------
// Launch
// ---------------------------------------------------------------------------
extern "C" void kernel_launch(void* const* d_in, const int* in_sizes, int n_in,
                              void* d_out, int out_size)
{
    const float* x     = (const float*)d_in[0];
    const float* T     = (const float*)d_in[1];
    const int*   mask  = (const int*)  d_in[2];
    const float* Wq    = (const float*)d_in[3];
    const float* bq    = (const float*)d_in[4];
    const float* Wk    = (const float*)d_in[5];
    const float* bk    = (const float*)d_in[6];
    const float* Wv    = (const float*)d_in[7];
    const float* bv    = (const float*)d_in[8];
    const float* alpha = (const float*)d_in[9];
    float* out = (float*)d_out;

    const int smem_g = (128 * XP + 64 * WP) * (int)sizeof(float);   // 67072
    cudaFuncSetAttribute(qkv_gemm,
                         cudaFuncAttributeMaxDynamicSharedMemorySize, smem_g);
    dim3 g1(HID / 128, (B_ * S_) / 128, 3);
    qkv_gemm<<<g1, 256, smem_g>>>(x, Wq, bq, Wk, bk, Wv, bv);

    const int smem_a = (64 * QP + 128 * KP + 128 * 64 + 128 * PP)
                       * (int)sizeof(float);                         // 165888
    cudaFuncSetAttribute(attn_kernel,
                         cudaFuncAttributeMaxDynamicSharedMemorySize, smem_a);
    dim3 g2(NH, S_ / 128, B_);
    attn_kernel<<<g2, 512, smem_a>>>(T, mask, alpha, out);
}

// round 11
// speedup vs baseline: 1.1763x; 1.1195x over previous
#include <cuda_runtime.h>
#include <math.h>

#define B_  4
#define S_  2048
#define HID 1024
#define NH  16
#define HD  64

typedef unsigned long long u64;
typedef unsigned int u32;

// Scratch (device globals: no allocation allowed in kernel_launch).
__device__ __align__(128) float g_Q[B_ * NH * S_ * HD];
__device__ __align__(128) float g_K[B_ * NH * S_ * HD];
__device__ __align__(128) float g_V[B_ * NH * S_ * HD];

// ---- packed f32x2 helpers -------------------------------------------------
__device__ __forceinline__ void ffma2(u64& acc, u64 a, u64 b) {
    asm("fma.rn.f32x2 %0, %1, %2, %0;" : "+l"(acc) : "l"(a), "l"(b));
}
__device__ __forceinline__ u64 mul2(u64 a, u64 b) {
    u64 r; asm("mul.rn.f32x2 %0, %1, %2;" : "=l"(r) : "l"(a), "l"(b)); return r;
}
__device__ __forceinline__ u64 dup2(float f) {
    u64 r; unsigned u = __float_as_uint(f);
    asm("mov.b64 %0, {%1, %1};" : "=l"(r) : "r"(u)); return r;
}
__device__ __forceinline__ u64 pk2(float a, float b) {
    u64 r;
    asm("mov.b64 %0, {%1, %2};" : "=l"(r)
        : "r"(__float_as_uint(a)), "r"(__float_as_uint(b)));
    return r;
}
__device__ __forceinline__ float2 unpk(u64 a) {
    unsigned lo, hi;
    asm("mov.b64 {%0, %1}, %2;" : "=r"(lo), "=r"(hi) : "l"(a));
    return make_float2(__uint_as_float(lo), __uint_as_float(hi));
}
__device__ __forceinline__ int kidx(int tx, int j) {
    return 2 * tx + (j & 1) + 32 * (j >> 1);
}

// ---- tf32 helpers ---------------------------------------------------------
__device__ __forceinline__ u32 tf32r(float f) {
    u32 r; asm("cvt.rna.tf32.f32 %0, %1;" : "=r"(r) : "f"(f)); return r;
}
__device__ __forceinline__ void split2(float v, u32& hi, u32& lo) {
    hi = tf32r(v);
    lo = tf32r(v - __uint_as_float(hi));
}
__device__ __forceinline__ void mma_tf32(float* c, u32 a0, u32 a1, u32 a2,
                                         u32 a3, u32 b0, u32 b1) {
    asm("mma.sync.aligned.m16n8k8.row.col.f32.tf32.tf32.f32 "
        "{%0,%1,%2,%3}, {%4,%5,%6,%7}, {%8,%9}, {%0,%1,%2,%3};"
        : "+f"(c[0]), "+f"(c[1]), "+f"(c[2]), "+f"(c[3])
        : "r"(a0), "r"(a1), "r"(a2), "r"(a3), "r"(b0), "r"(b1));
}

// ---------------------------------------------------------------------------
// Kernel 1: tf32 HMMA projection GEMM; fp32 smem, in-register hi/lo split,
// 3 accumulating passes. Block 128m x 128n, 256 threads, warp = 64m x 32n.
// ---------------------------------------------------------------------------
#define XP 68     // xs row pad: bank = 4*gr + gc -> conflict-free frag gather
#define WP 136    // ws row pad: bank = 8*gc + gr -> conflict-free frag gather

__global__ __launch_bounds__(256, 2) void qkv_gemm_tc(
    const float* __restrict__ x,
    const float* __restrict__ Wq, const float* __restrict__ bq,
    const float* __restrict__ Wk, const float* __restrict__ bk,
    const float* __restrict__ Wv, const float* __restrict__ bv)
{
    extern __shared__ float smg[];
    float* xs = smg;              // [128][XP]  row-major [m][k]
    float* ws = smg + 128 * XP;   // [64][WP]   [k][n]

    const int z = blockIdx.z;
    const float* W    = (z == 0) ? Wq : (z == 1) ? Wk : Wv;
    const float* bias = (z == 0) ? bq : (z == 1) ? bk : bv;
    float* dst        = (z == 0) ? g_Q : (z == 1) ? g_K : g_V;

    const int n0 = blockIdx.x * 128;
    const int m0 = blockIdx.y * 128;
    const int tid = threadIdx.x;
    const int lane = tid & 31;
    const int wid = tid >> 5;
    const int wm = wid & 1;         // 2 m-halves of 64
    const int wn = wid >> 1;        // 4 n-quarters of 32
    const int gr = lane >> 2;       // 0..7
    const int gc = lane & 3;        // 0..3

    float acc[4][4][4] = {};        // [tm][tn][c0..c3]

    for (int k0 = 0; k0 < HID; k0 += 64) {
        __syncthreads();
        #pragma unroll
        for (int i = 0; i < 8; i++) {
            int lin = tid + i * 256;
            int r = lin >> 4, c = lin & 15;          // x: 128 rows x 16 chunks
            float4 xv = *(const float4*)&x[(size_t)(m0 + r) * HID + k0 + c * 4];
            xs[r * XP + c * 4 + 0] = xv.x;
            xs[r * XP + c * 4 + 1] = xv.y;
            xs[r * XP + c * 4 + 2] = xv.z;
            xs[r * XP + c * 4 + 3] = xv.w;
            int rw = lin >> 5, cw = lin & 31;        // W: 64 rows x 32 chunks
            float4 wv = *(const float4*)&W[(size_t)(k0 + rw) * HID + n0 + cw * 4];
            *(float4*)&ws[rw * WP + cw * 4] = wv;
        }
        __syncthreads();

        #pragma unroll
        for (int ks = 0; ks < 8; ks++) {
            const int kk = ks * 8;
            // B fragments (4 n-tiles), converted in registers
            u32 bh[4][2], bl[4][2];
            #pragma unroll
            for (int tn = 0; tn < 4; tn++) {
                int ccol = wn * 32 + tn * 8 + gr;
                split2(ws[(kk + gc)     * WP + ccol], bh[tn][0], bl[tn][0]);
                split2(ws[(kk + gc + 4) * WP + ccol], bh[tn][1], bl[tn][1]);
            }
            #pragma unroll
            for (int tm = 0; tm < 4; tm++) {
                int r = wm * 64 + tm * 16 + gr;
                u32 ah[4], al[4];
                split2(xs[(r)     * XP + kk + gc],     ah[0], al[0]);
                split2(xs[(r + 8) * XP + kk + gc],     ah[1], al[1]);
                split2(xs[(r)     * XP + kk + gc + 4], ah[2], al[2]);
                split2(xs[(r + 8) * XP + kk + gc + 4], ah[3], al[3]);
                #pragma unroll
                for (int tn = 0; tn < 4; tn++) {
                    float* c = acc[tm][tn];
                    mma_tf32(c, ah[0], ah[1], ah[2], ah[3],
                             bh[tn][0], bh[tn][1]);
                    mma_tf32(c, ah[0], ah[1], ah[2], ah[3],
                             bl[tn][0], bl[tn][1]);
                    mma_tf32(c, al[0], al[1], al[2], al[3],
                             bh[tn][0], bh[tn][1]);
                }
            }
        }
    }

    // Epilogue: scatter into [B,H,S,D] with bias (layout verified in R9).
    #pragma unroll
    for (int tm = 0; tm < 4; tm++) {
        #pragma unroll
        for (int half = 0; half < 2; half++) {
            int m = m0 + wm * 64 + tm * 16 + gr + half * 8;
            int b = m >> 11;
            int s = m & (S_ - 1);
            #pragma unroll
            for (int tn = 0; tn < 4; tn++) {
                int n = n0 + wn * 32 + tn * 8 + 2 * gc;
                float2 bb = *(const float2*)&bias[n];
                float2 r;
                r.x = acc[tm][tn][half * 2 + 0] + bb.x;
                r.y = acc[tm][tn][half * 2 + 1] + bb.y;
                int h = n >> 6, d = n & 63;
                *(float2*)&dst[(((size_t)b * NH + h) * S_ + s) * HD + d] = r;
            }
        }
    }
}

// ---------------------------------------------------------------------------
// Kernel 2: flash attention (exact Round-4 kernel — proven 2611us config).
// ---------------------------------------------------------------------------
#define QP 130
#define KP 65
#define PP 130

__global__ __launch_bounds__(256, 1) void attn_kernel(
    const float* __restrict__ T,
    const int*   __restrict__ mask,
    const float* __restrict__ alpha_p,
    float*       __restrict__ out)
{
    extern __shared__ float sma[];
    float* Qt = sma;
    float* Ks = Qt + 64 * QP;
    float* Vs = Ks + 128 * KP;
    float* Pt = Vs + 128 * 64;

    const int h  = blockIdx.x;
    const int q0 = blockIdx.y * 128;
    const int b  = blockIdx.z;
    const int tid = threadIdx.x;
    const int tx = tid & 15;
    const int ty = tid >> 4;

    const float nalpha = -fabsf(*alpha_p);
    const float* Qg = g_Q + ((size_t)b * NH + h) * S_ * HD;
    const float* Kg = g_K + ((size_t)b * NH + h) * S_ * HD;
    const float* Vg = g_V + ((size_t)b * NH + h) * S_ * HD;
    const float* Tb = T    + (size_t)b * S_ * S_;
    const int*   Mb = mask + (size_t)b * S_ * S_;

    #pragma unroll
    for (int i = 0; i < 8; i++) {
        int lin = tid + i * 256;
        int q = lin >> 4, c = lin & 15;
        float4 v = *(const float4*)&Qg[(size_t)(q0 + q) * HD + c * 4];
        Qt[(c * 4 + 0) * QP + q] = v.x;
        Qt[(c * 4 + 1) * QP + q] = v.y;
        Qt[(c * 4 + 2) * QP + q] = v.z;
        Qt[(c * 4 + 3) * QP + q] = v.w;
    }

    float m_run[8], l_run[8];
    u64 o2[4][4] = {};
    #pragma unroll
    for (int r = 0; r < 8; r++) { m_run[r] = -INFINITY; l_run[r] = 0.f; }

    for (int k0 = 0; k0 < S_; k0 += 128) {
        __syncthreads();
        #pragma unroll
        for (int i = 0; i < 8; i++) {
            int lin = tid + i * 256;
            int k = lin >> 4, c = lin & 15;
            float4 kv = *(const float4*)&Kg[(size_t)(k0 + k) * HD + c * 4];
            Ks[k * KP + c * 4 + 0] = kv.x;
            Ks[k * KP + c * 4 + 1] = kv.y;
            Ks[k * KP + c * 4 + 2] = kv.z;
            Ks[k * KP + c * 4 + 3] = kv.w;
            float4 vv = *(const float4*)&Vg[(size_t)(k0 + k) * HD + c * 4];
            *(float4*)&Vs[k * 64 + c * 4] = vv;
        }
        __syncthreads();

        u64 acc2[4][8] = {};
        #pragma unroll 8
        for (int c = 0; c < 64; c++) {
            u64 qp[4];
            #pragma unroll
            for (int m = 0; m < 4; m++)
                qp[m] = *(const u64*)&Qt[c * QP + ty * 8 + 2 * m];
            u64 kd[8];
            #pragma unroll
            for (int j = 0; j < 8; j++)
                kd[j] = dup2(Ks[kidx(tx, j) * KP + c]);
            #pragma unroll
            for (int m = 0; m < 4; m++)
                #pragma unroll
                for (int j = 0; j < 8; j++)
                    ffma2(acc2[m][j], qp[m], kd[j]);
        }

        #pragma unroll
        for (int m = 0; m < 4; m++) {
            float2 sc[8];
            #pragma unroll
            for (int j = 0; j < 8; j++) sc[j] = unpk(acc2[m][j]);
            float corr2[2];
            #pragma unroll
            for (int e = 0; e < 2; e++) {
                int r = 2 * m + e;
                int qg = q0 + ty * 8 + r;
                float v[8];
                #pragma unroll
                for (int jj = 0; jj < 4; jj++) {
                    size_t off = (size_t)qg * S_ + k0 + 2 * tx + 32 * jj;
                    float2 t2 = *(const float2*)&Tb[off];
                    int2  mm2 = *(const int2*)  &Mb[off];
                    float s0 = e ? sc[2 * jj].y     : sc[2 * jj].x;
                    float s1 = e ? sc[2 * jj + 1].y : sc[2 * jj + 1].x;
                    v[2 * jj]     = (mm2.x == 0) ? -1e9f : s0 * 0.125f + nalpha * t2.x;
                    v[2 * jj + 1] = (mm2.y == 0) ? -1e9f : s1 * 0.125f + nalpha * t2.y;
                }
                float mloc = v[0];
                #pragma unroll
                for (int j = 1; j < 8; j++) mloc = fmaxf(mloc, v[j]);
                mloc = fmaxf(mloc, __shfl_xor_sync(0xFFFFFFFFu, mloc, 1));
                mloc = fmaxf(mloc, __shfl_xor_sync(0xFFFFFFFFu, mloc, 2));
                mloc = fmaxf(mloc, __shfl_xor_sync(0xFFFFFFFFu, mloc, 4));
                mloc = fmaxf(mloc, __shfl_xor_sync(0xFFFFFFFFu, mloc, 8));
                float mnew = fmaxf(m_run[r], mloc);
                float corr = __expf(m_run[r] - mnew);
                float ps = 0.f;
                #pragma unroll
                for (int j = 0; j < 8; j++) {
                    v[j] = __expf(v[j] - mnew);
                    ps += v[j];
                }
                ps += __shfl_xor_sync(0xFFFFFFFFu, ps, 1);
                ps += __shfl_xor_sync(0xFFFFFFFFu, ps, 2);
                ps += __shfl_xor_sync(0xFFFFFFFFu, ps, 4);
                ps += __shfl_xor_sync(0xFFFFFFFFu, ps, 8);
                l_run[r] = l_run[r] * corr + ps;
                m_run[r] = mnew;
                corr2[e] = corr;
                #pragma unroll
                for (int j = 0; j < 8; j++)
                    Pt[kidx(tx, j) * PP + ty * 8 + r] = v[j];
            }
            u64 c2 = pk2(corr2[0], corr2[1]);
            #pragma unroll
            for (int j = 0; j < 4; j++) o2[m][j] = mul2(o2[m][j], c2);
        }
        __syncthreads();

        #pragma unroll 4
        for (int k = 0; k < 128; k++) {
            u64 p2[4];
            #pragma unroll
            for (int m = 0; m < 4; m++)
                p2[m] = *(const u64*)&Pt[k * PP + ty * 8 + 2 * m];
            u64 vd[4];
            #pragma unroll
            for (int j = 0; j < 4; j++)
                vd[j] = dup2(Vs[k * 64 + tx + 16 * j]);
            #pragma unroll
            for (int m = 0; m < 4; m++)
                #pragma unroll
                for (int j = 0; j < 4; j++)
                    ffma2(o2[m][j], p2[m], vd[j]);
        }
    }

    #pragma unroll
    for (int m = 0; m < 4; m++) {
        float inv0 = 1.f / l_run[2 * m];
        float inv1 = 1.f / l_run[2 * m + 1];
        int s0 = q0 + ty * 8 + 2 * m;
        #pragma unroll
        for (int j = 0; j < 4; j++) {
            float2 ov = unpk(o2[m][j]);
            int d = h * HD + tx + 16 * j;
            out[((size_t)b * S_ + s0)     * HID + d] = ov.x * inv0;
            out[((size_t)b * S_ + s0 + 1) * HID + d] = ov.y * inv1;
        }
    }
}

// ---------------------------------------------------------------------------
// Launch
// ---------------------------------------------------------------------------
extern "C" void kernel_launch(void* const* d_in, const int* in_sizes, int n_in,
                              void* d_out, int out_size)
{
    const float* x     = (const float*)d_in[0];
    const float* T     = (const float*)d_in[1];
    const int*   mask  = (const int*)  d_in[2];
    const float* Wq    = (const float*)d_in[3];
    const float* bq    = (const float*)d_in[4];
    const float* Wk    = (const float*)d_in[5];
    const float* bk    = (const float*)d_in[6];
    const float* Wv    = (const float*)d_in[7];
    const float* bv    = (const float*)d_in[8];
    const float* alpha = (const float*)d_in[9];
    float* out = (float*)d_out;

    const int smem_g = (128 * XP + 64 * WP) * (int)sizeof(float);   // 139?KB->69.6KB
    cudaFuncSetAttribute(qkv_gemm_tc,
                         cudaFuncAttributeMaxDynamicSharedMemorySize, smem_g);
    dim3 g1(HID / 128, (B_ * S_) / 128, 3);
    qkv_gemm_tc<<<g1, 256, smem_g>>>(x, Wq, bq, Wk, bk, Wv, bv);

    const int smem_a = (64 * QP + 128 * KP + 128 * 64 + 128 * PP)
                       * (int)sizeof(float);                         // 165888
    cudaFuncSetAttribute(attn_kernel,
                         cudaFuncAttributeMaxDynamicSharedMemorySize, smem_a);
    dim3 g2(NH, S_ / 128, B_);
    attn_kernel<<<g2, 256, smem_a>>>(T, mask, alpha, out);
}